// round 3
// baseline (speedup 1.0000x reference)
#include <cuda_runtime.h>
#include <cstdint>
#include <math.h>

// Problem constants
constexpr int   D       = 2048;
constexpr int   F       = 256;
constexpr float ALPHA   = 0.005f;   // SINKHORN_ALPHA
constexpr float STOPTHR = 0.005f;
constexpr float EPSF    = 1e-16f;
constexpr int   MAXIT   = 500;

// Launch shapes
constexpr int NB  = 128;          // persistent sinkhorn blocks (one per SM, all co-resident)
constexpr int NT  = 256;          // threads per block
constexpr int RPB = D / NB;       // 16 rows per block
constexpr int NKB = 256;          // KL reduction blocks

// ---------------- device scratch (static: no allocations allowed) ----------------
__device__ float  d_K[(size_t)D * D];     // 16 MB: K = exp(-alpha * C), symmetric
__device__ float  d_G[(size_t)D * D];     // 16 MB: Ghat = ehat @ ehat^T (cosine sims)
__device__ float  d_ehat[D * F];          // row-normalized embeddings
__device__ float  d_sq[D];                // ||theta_i||^2
__device__ float  d_invr[D];              // 1 / rowsum(Ghat)
__device__ float  d_u[D];
__device__ float  d_v[D];
__device__ float  d_errpart[10 * NB];     // per-block err partials, one slot set per check
__device__ double d_part[3 * NKB];        // KL reduction partials: [S | sumP | kl0]
__device__ unsigned long long g_arrive;   // cumulative grid-barrier arrivals

// ---------------- helpers ----------------
__device__ __forceinline__ float warp_red(float s) {
#pragma unroll
    for (int o = 16; o; o >>= 1) s += __shfl_xor_sync(0xffffffffu, s, o);
    return s;
}

// Cumulative-counter grid barrier. g_arrive is zeroed by prep() (prior launch in
// stream order), so epochs count from 0 each replay. Release/acquire via
// __threadfence around the atomic; __syncthreads makes it block-wide.
__device__ __forceinline__ void gbar(unsigned long long target) {
    __syncthreads();
    if (threadIdx.x == 0) {
        __threadfence();
        atomicAdd(&g_arrive, 1ULL);
        while (*(volatile unsigned long long*)&g_arrive < target) __nanosleep(64);
        __threadfence();
    }
    __syncthreads();
}

// ---------------- prep: sq, ehat, barrier-counter reset ----------------
__global__ void __launch_bounds__(F) prep(const float* __restrict__ theta,
                                          const float* __restrict__ emb) {
    const int row = blockIdx.x, tid = threadIdx.x;
    if (row == 0 && tid == 0) g_arrive = 0ULL;

    const float t = theta[row * F + tid];
    const float e = emb[row * F + tid];
    float a = t * t, b = e * e;
#pragma unroll
    for (int o = 16; o; o >>= 1) {
        a += __shfl_xor_sync(0xffffffffu, a, o);
        b += __shfl_xor_sync(0xffffffffu, b, o);
    }
    __shared__ float sa[8], sb[8];
    __shared__ float s_inv;
    const int wid = tid >> 5, lane = tid & 31;
    if (lane == 0) { sa[wid] = a; sb[wid] = b; }
    __syncthreads();
    if (tid == 0) {
        float ta = 0.f, tb = 0.f;
#pragma unroll
        for (int i = 0; i < 8; i++) { ta += sa[i]; tb += sb[i]; }
        d_sq[row] = ta;
        s_inv = 1.0f / sqrtf(tb);
    }
    __syncthreads();
    d_ehat[row * F + tid] = e * s_inv;
}

// ---------------- tiled fp32 GEMM: Out = X @ X^T (64x64 tile, 4x4/thread) ---------
// MODE 0: X = theta param,  Out = K with distance/exp epilogue
// MODE 1: X = d_ehat,       Out = Ghat (plain)
template <int MODE>
__global__ void __launch_bounds__(256) gemm_xxt(const float* __restrict__ Xin) {
    const float* __restrict__ X = (MODE == 0) ? Xin : (const float*)d_ehat;
    __shared__ float As[16][64];
    __shared__ float Bs[16][64];
    const int tid = threadIdx.x;
    const int ib = blockIdx.y, jb = blockIdx.x;
    const int lr = tid >> 2;          // 0..63
    const int lc = (tid & 3) * 4;     // 0,4,8,12
    const int ty = tid >> 4, tx = tid & 15;

    float acc[4][4];
#pragma unroll
    for (int i = 0; i < 4; i++)
#pragma unroll
        for (int j = 0; j < 4; j++) acc[i][j] = 0.0f;

    const float* Arow = X + (size_t)(ib * 64 + lr) * F;
    const float* Brow = X + (size_t)(jb * 64 + lr) * F;

    for (int k0 = 0; k0 < F; k0 += 16) {
        const float4 av = *(const float4*)(Arow + k0 + lc);
        const float4 bv = *(const float4*)(Brow + k0 + lc);
        As[lc + 0][lr] = av.x; As[lc + 1][lr] = av.y; As[lc + 2][lr] = av.z; As[lc + 3][lr] = av.w;
        Bs[lc + 0][lr] = bv.x; Bs[lc + 1][lr] = bv.y; Bs[lc + 2][lr] = bv.z; Bs[lc + 3][lr] = bv.w;
        __syncthreads();
#pragma unroll
        for (int kk = 0; kk < 16; kk++) {
            float a[4], b[4];
#pragma unroll
            for (int i = 0; i < 4; i++) a[i] = As[kk][ty * 4 + i];
#pragma unroll
            for (int j = 0; j < 4; j++) b[j] = Bs[kk][tx * 4 + j];
#pragma unroll
            for (int i = 0; i < 4; i++)
#pragma unroll
                for (int j = 0; j < 4; j++) acc[i][j] = fmaf(a[i], b[j], acc[i][j]);
        }
        __syncthreads();
    }

    const int rb = ib * 64 + ty * 4, cb = jb * 64 + tx * 4;
#pragma unroll
    for (int i = 0; i < 4; i++) {
#pragma unroll
        for (int j = 0; j < 4; j++) {
            const size_t o = (size_t)(rb + i) * D + (cb + j);
            if (MODE == 0) {
                const float c = fmaxf(d_sq[rb + i] + d_sq[cb + j] - 2.0f * acc[i][j], 0.0f);
                d_K[o] = expf(-ALPHA * c);
            } else {
                d_G[o] = acc[i][j];
            }
        }
    }
}

// ---------------- rowsum of Ghat -> invr ----------------
__global__ void __launch_bounds__(NT) rowsum() {
    const int row = blockIdx.x, tid = threadIdx.x;
    const float4* g = (const float4*)(d_G + (size_t)row * D);
    float s = 0.f;
#pragma unroll
    for (int i = 0; i < (D / 4) / NT; i++) {
        const float4 v = g[tid + i * NT];
        s += (v.x + v.y) + (v.z + v.w);
    }
    s = warp_red(s);
    __shared__ float sw[8];
    if ((tid & 31) == 0) sw[tid >> 5] = s;
    __syncthreads();
    if (tid == 0) {
        float t = 0.f;
#pragma unroll
        for (int i = 0; i < 8; i++) t += sw[i];
        d_invr[row] = 1.0f / t;
    }
}

// one row-dot: dot(K[row,:], sx[0:D]) reduced across the warp
__device__ __forceinline__ float row_dot(const float* __restrict__ Krow,
                                         const float* sx, int lane) {
    const float4* Kr = (const float4*)Krow;
    const float4* xr = (const float4*)sx;
    float s = 0.f;
#pragma unroll
    for (int it = 0; it < D / 128; it++) {   // 16 float4 per lane
        const float4 k4 = __ldg(Kr + lane + 32 * it);
        const float4 x4 = xr[lane + 32 * it];
        s = fmaf(k4.x, x4.x, s);
        s = fmaf(k4.y, x4.y, s);
        s = fmaf(k4.z, x4.z, s);
        s = fmaf(k4.w, x4.w, s);
    }
    return warp_red(s);
}

// ---------------- persistent Sinkhorn (K symmetric => K^T u == K u) ----------------
__global__ void __launch_bounds__(NT, 1) sinkhorn_kernel() {
    __shared__ float sx[D];          // 8 KB: current vector
    __shared__ float sred[RPB];
    const int tid = threadIdx.x, bid = blockIdx.x;
    const int wid = tid >> 5, lane = tid & 31;
    const int row0 = bid * RPB + wid * 2;   // 8 warps x 2 rows = 16 rows/block
    const float AB = 1.0f / (float)D;       // a == b == 1/D

    if (tid < RPB) { d_u[bid * RPB + tid] = 1.0f; d_v[bid * RPB + tid] = 1.0f; }

    unsigned long long ep = 1;
    gbar(ep * (unsigned long long)NB);      // u,v init visible everywhere

    float err = 1.0f;
    int cpt = 0;
    while (err > STOPTHR && cpt < MAXIT) {
        // v = b / (K u + eps)
        for (int i = tid; i < D / 4; i += NT)
            ((float4*)sx)[i] = __ldcg(((const float4*)d_u) + i);
        __syncthreads();
#pragma unroll
        for (int rr = 0; rr < 2; rr++) {
            const float s = row_dot(d_K + (size_t)(row0 + rr) * D, sx, lane);
            if (lane == 0) d_v[row0 + rr] = AB / (s + EPSF);
        }
        ep++; gbar(ep * (unsigned long long)NB);

        // u = a / (K v + eps)
        for (int i = tid; i < D / 4; i += NT)
            ((float4*)sx)[i] = __ldcg(((const float4*)d_v) + i);
        __syncthreads();
#pragma unroll
        for (int rr = 0; rr < 2; rr++) {
            const float s = row_dot(d_K + (size_t)(row0 + rr) * D, sx, lane);
            if (lane == 0) d_u[row0 + rr] = AB / (s + EPSF);
        }
        ep++; gbar(ep * (unsigned long long)NB);

        cpt++;
        if (cpt % 50 == 1) {
            // err = sum_i | v_i * (K u_new)_i - b |   (only evaluated at checks)
            for (int i = tid; i < D / 4; i += NT)
                ((float4*)sx)[i] = __ldcg(((const float4*)d_u) + i);
            __syncthreads();
#pragma unroll
            for (int rr = 0; rr < 2; rr++) {
                const float s = row_dot(d_K + (size_t)(row0 + rr) * D, sx, lane);
                if (lane == 0)
                    sred[wid * 2 + rr] = fabsf(__ldcg(&d_v[row0 + rr]) * s - AB);
            }
            __syncthreads();
            const int chk = cpt / 50;       // 0..9
            if (tid == 0) {
                float e = 0.f;
#pragma unroll
                for (int i = 0; i < RPB; i++) e += sred[i];
                d_errpart[chk * NB + bid] = e;
            }
            ep++; gbar(ep * (unsigned long long)NB);
            // deterministic identical reduction in every block -> uniform control flow
            float e = 0.f;
            for (int i = 0; i < NB; i++) e += __ldcg(&d_errpart[chk * NB + i]);
            err = e;
        }
    }
    // final u, v left in global memory
}

// ---------------- KL reduction ----------------
// Q~_ij = max(u_i K_ij v_j, 1e-6), S = sum Q~, P_ij = Ghat_ij*(invr_i+invr_j)/2
// kl = sum P*(log P - log Q~) + log(S) * sum P
__global__ void __launch_bounds__(NT) kl_partial() {
    const int tid = threadIdx.x;
    const size_t total = (size_t)D * D;
    const size_t stride = (size_t)gridDim.x * NT;
    double sS = 0.0, sP = 0.0, sK = 0.0;
    for (size_t idx = (size_t)blockIdx.x * NT + tid; idx < total; idx += stride) {
        const int i = (int)(idx >> 11);
        const int j = (int)(idx & (size_t)(D - 1));
        const float k = d_K[idx];
        const float q = fmaxf(d_u[i] * k * d_v[j], 1e-6f);
        const float p = d_G[idx] * (0.5f * (d_invr[i] + d_invr[j]));
        sS += (double)q;
        sP += (double)p;
        sK += (double)(p * (logf(p) - logf(q)));
    }
    __shared__ double sd[NT];
    double vals[3] = {sS, sP, sK};
#pragma unroll
    for (int t = 0; t < 3; t++) {
        sd[tid] = vals[t];
        __syncthreads();
        for (int o = NT / 2; o; o >>= 1) {
            if (tid < o) sd[tid] += sd[tid + o];
            __syncthreads();
        }
        if (tid == 0) d_part[t * NKB + blockIdx.x] = sd[0];
        __syncthreads();
    }
}

__global__ void finalize(float* out) {
    if (threadIdx.x == 0) {
        double S = 0.0, P = 0.0, K = 0.0;
        for (int i = 0; i < NKB; i++) {
            S += d_part[i];
            P += d_part[NKB + i];
            K += d_part[2 * NKB + i];
        }
        out[0] = (float)(K + log(S) * P);
    }
}

// ---------------- launch ----------------
extern "C" void kernel_launch(void* const* d_in, const int* in_sizes, int n_in,
                              void* d_out, int out_size) {
    const float* theta = (const float*)d_in[0];
    const float* emb   = (const float*)d_in[1];
    float* out = (float*)d_out;

    prep<<<D, F>>>(theta, emb);
    dim3 g(D / 64, D / 64);
    gemm_xxt<0><<<g, 256>>>(theta);
    gemm_xxt<1><<<g, 256>>>(theta);   // reads d_ehat internally
    rowsum<<<D, NT>>>();
    sinkhorn_kernel<<<NB, NT>>>();
    kl_partial<<<NKB, NT>>>();
    finalize<<<1, 32>>>(out);
}

// round 4
// speedup vs baseline: 1.7396x; 1.7396x over previous
#include <cuda_runtime.h>
#include <cstdint>
#include <math.h>

// Problem constants
constexpr int   D       = 2048;
constexpr int   F       = 256;
constexpr float ALPHA   = 0.005f;   // SINKHORN_ALPHA
constexpr float STOPTHR = 0.005f;
constexpr float EPSF    = 1e-16f;
constexpr int   MAXIT   = 500;

// Launch shapes
constexpr int NB   = 128;         // persistent sinkhorn blocks (one per SM, co-resident)
constexpr int NT   = 256;         // threads per block
constexpr int RPB  = D / NB;      // 16 rows per block
constexpr int NKB  = 256;         // KL reduction blocks
constexpr int NBLK = 136;         // triangular 128x128 tile count: 16*17/2

// ---------------- device scratch (static: no allocations allowed) ----------------
__device__ float  d_K[(size_t)D * D];     // 16 MB: K = exp(-alpha * C), symmetric
__device__ float  d_G[(size_t)D * D];     // 16 MB: Ghat = ehat @ ehat^T, symmetric
__device__ float  d_ehat[D * F];          // row-normalized embeddings
__device__ float  d_sq[D];                // ||theta_i||^2
__device__ float  d_invr[D];              // 1 / rowsum(Ghat)
__device__ float  d_u[D];
__device__ float  d_v[D];
__device__ float  d_errpart[12 * NB];     // per-block err partials per check
__device__ double d_part[3 * NKB];        // KL partials: [S | sumP | kl0]
__device__ unsigned d_flags[NB];          // distributed grid-barrier flags (epoch counters)

// ---------------- helpers ----------------
__device__ __forceinline__ float warp_red(float s) {
#pragma unroll
    for (int o = 16; o; o >>= 1) s += __shfl_xor_sync(0xffffffffu, s, o);
    return s;
}

// Distributed flag grid barrier. Each block publishes its epoch with a release
// (__threadfence + __stcg); warp 0 of every block polls all NB flags via __ldcg
// (4 flags per lane). No atomic contention, no single-address serialization.
__device__ __forceinline__ void gbar(unsigned ep, int tid, int bid) {
    __syncthreads();
    if (tid == 0) {
        __threadfence();
        __stcg(&d_flags[bid], ep);
    }
    if (tid < 32) {
        const int lane = tid;
        for (;;) {
            int ok = 1;
#pragma unroll
            for (int k = 0; k < NB / 32; k++)
                if (__ldcg(&d_flags[lane * (NB / 32) + k]) < ep) ok = 0;
            if (__all_sync(0xffffffffu, ok)) break;
            __nanosleep(32);
        }
        __threadfence();
    }
    __syncthreads();
}

// ---------------- prep: sq, ehat, flag reset ----------------
__global__ void __launch_bounds__(F) prep(const float* __restrict__ theta,
                                          const float* __restrict__ emb) {
    const int row = blockIdx.x, tid = threadIdx.x;
    if (tid == 0 && row < NB) d_flags[row] = 0u;

    const float t = theta[row * F + tid];
    const float e = emb[row * F + tid];
    float a = t * t, b = e * e;
#pragma unroll
    for (int o = 16; o; o >>= 1) {
        a += __shfl_xor_sync(0xffffffffu, a, o);
        b += __shfl_xor_sync(0xffffffffu, b, o);
    }
    __shared__ float sa[8], sb[8];
    __shared__ float s_inv;
    const int wid = tid >> 5, lane = tid & 31;
    if (lane == 0) { sa[wid] = a; sb[wid] = b; }
    __syncthreads();
    if (tid == 0) {
        float ta = 0.f, tb = 0.f;
#pragma unroll
        for (int i = 0; i < 8; i++) { ta += sa[i]; tb += sb[i]; }
        d_sq[row] = ta;
        s_inv = 1.0f / sqrtf(tb);
    }
    __syncthreads();
    d_ehat[row * F + tid] = e * s_inv;
}

// ---------------- symmetric fused GEMM: K and Ghat in one launch --------------
// bid in [0, NBLK)        : K    = exp(-alpha * max(sq_i + sq_j - 2*theta theta^T, 0))
// bid in [NBLK, 2*NBLK)   : Ghat = ehat ehat^T
// 128x128 tile, 8x8 per thread, lower-triangle blocks only; mirror store.
__global__ void __launch_bounds__(256, 2) gemm_sym(const float* __restrict__ theta) {
    const int bid = blockIdx.x;
    const bool modeK = (bid < NBLK);
    const int tb = modeK ? bid : bid - NBLK;
    const float* __restrict__ X = modeK ? theta : (const float*)d_ehat;
    float* __restrict__ Out = modeK ? d_K : d_G;

    // triangular index -> (ib, jb), ib >= jb
    int ib = (int)((sqrtf(8.0f * (float)tb + 1.0f) - 1.0f) * 0.5f);
    while ((ib + 1) * (ib + 2) / 2 <= tb) ib++;
    while (ib * (ib + 1) / 2 > tb) ib--;
    const int jb = tb - ib * (ib + 1) / 2;

    __shared__ float As[16][128];
    __shared__ float Bs[16][128];
    const int tid = threadIdx.x;
    const int tx = tid & 15, ty = tid >> 4;
    const int r0 = ib * 128, c0 = jb * 128;

    float acc[8][8];
#pragma unroll
    for (int i = 0; i < 8; i++)
#pragma unroll
        for (int j = 0; j < 8; j++) acc[i][j] = 0.0f;

    for (int k0 = 0; k0 < F; k0 += 16) {
#pragma unroll
        for (int q = 0; q < 2; q++) {
            const int idx = tid * 2 + q;        // 0..511
            const int row = idx >> 2;           // 0..127
            const int kk  = (idx & 3) * 4;      // 0,4,8,12
            const float4 av = *(const float4*)(X + (size_t)(r0 + row) * F + k0 + kk);
            As[kk + 0][row] = av.x; As[kk + 1][row] = av.y;
            As[kk + 2][row] = av.z; As[kk + 3][row] = av.w;
            const float4 bv = *(const float4*)(X + (size_t)(c0 + row) * F + k0 + kk);
            Bs[kk + 0][row] = bv.x; Bs[kk + 1][row] = bv.y;
            Bs[kk + 2][row] = bv.z; Bs[kk + 3][row] = bv.w;
        }
        __syncthreads();
#pragma unroll
        for (int kk = 0; kk < 16; kk++) {
            float a[8], b[8];
#pragma unroll
            for (int i = 0; i < 8; i++) a[i] = As[kk][ty * 8 + i];
#pragma unroll
            for (int j = 0; j < 8; j++) b[j] = Bs[kk][tx * 8 + j];
#pragma unroll
            for (int i = 0; i < 8; i++)
#pragma unroll
                for (int j = 0; j < 8; j++) acc[i][j] = fmaf(a[i], b[j], acc[i][j]);
        }
        __syncthreads();
    }

    // epilogue: transform acc in place for K mode
    if (modeK) {
        float sr[8], sc[8];
#pragma unroll
        for (int i = 0; i < 8; i++) sr[i] = d_sq[r0 + ty * 8 + i];
#pragma unroll
        for (int j = 0; j < 8; j++) sc[j] = d_sq[c0 + tx * 8 + j];
#pragma unroll
        for (int i = 0; i < 8; i++)
#pragma unroll
            for (int j = 0; j < 8; j++) {
                const float c = fmaxf(sr[i] + sc[j] - 2.0f * acc[i][j], 0.0f);
                acc[i][j] = __expf(-ALPHA * c);
            }
    }

    // normal store (rows of the lower-triangle tile)
#pragma unroll
    for (int i = 0; i < 8; i++) {
        float* p = Out + (size_t)(r0 + ty * 8 + i) * D + c0 + tx * 8;
        *(float4*)(p)     = make_float4(acc[i][0], acc[i][1], acc[i][2], acc[i][3]);
        *(float4*)(p + 4) = make_float4(acc[i][4], acc[i][5], acc[i][6], acc[i][7]);
    }
    // mirror store (upper-triangle image; identical values on diagonal blocks)
#pragma unroll
    for (int j = 0; j < 8; j++) {
        float* p = Out + (size_t)(c0 + tx * 8 + j) * D + r0 + ty * 8;
        *(float4*)(p)     = make_float4(acc[0][j], acc[1][j], acc[2][j], acc[3][j]);
        *(float4*)(p + 4) = make_float4(acc[4][j], acc[5][j], acc[6][j], acc[7][j]);
    }
}

// ---------------- rowsum of Ghat -> invr (warp per row, L2-resident) -----------
__global__ void __launch_bounds__(256) rowsum() {
    const int row  = blockIdx.x * 8 + (threadIdx.x >> 5);
    const int lane = threadIdx.x & 31;
    const float4* g = (const float4*)(d_G + (size_t)row * D);
    float s = 0.f;
#pragma unroll
    for (int it = 0; it < D / 128; it++) {
        const float4 v = g[lane + 32 * it];
        s += (v.x + v.y) + (v.z + v.w);
    }
    s = warp_red(s);
    if (lane == 0) d_invr[row] = 1.0f / s;
}

// two interleaved row-dots against smem vector (2x MLP on K loads)
__device__ __forceinline__ void row_dot2(const float* __restrict__ K0,
                                         const float* __restrict__ K1,
                                         const float* sx, int lane,
                                         float& o0, float& o1) {
    const float4* a = (const float4*)K0;
    const float4* b = (const float4*)K1;
    const float4* x = (const float4*)sx;
    float s0 = 0.f, s1 = 0.f;
#pragma unroll
    for (int it = 0; it < D / 128; it++) {
        const float4 k0 = __ldg(a + lane + 32 * it);
        const float4 k1 = __ldg(b + lane + 32 * it);
        const float4 xv = x[lane + 32 * it];
        s0 = fmaf(k0.x, xv.x, s0); s1 = fmaf(k1.x, xv.x, s1);
        s0 = fmaf(k0.y, xv.y, s0); s1 = fmaf(k1.y, xv.y, s1);
        s0 = fmaf(k0.z, xv.z, s0); s1 = fmaf(k1.z, xv.z, s1);
        s0 = fmaf(k0.w, xv.w, s0); s1 = fmaf(k1.w, xv.w, s1);
    }
    o0 = warp_red(s0);
    o1 = warp_red(s1);
}

// ---------------- persistent Sinkhorn (K symmetric => K^T u == K u) -------------
__global__ void __launch_bounds__(NT, 1) sinkhorn_kernel() {
    __shared__ float sx[D];           // 8 KB: current vector
    __shared__ float sred[RPB];
    const int tid = threadIdx.x, bid = blockIdx.x;
    const int wid = tid >> 5, lane = tid & 31;
    const int row0 = bid * RPB + wid * 2;   // 8 warps x 2 rows
    const float AB = 1.0f / (float)D;       // a == b == 1/D

    if (tid < RPB) { d_u[bid * RPB + tid] = 1.0f; d_v[bid * RPB + tid] = 1.0f; }

    unsigned ep = 1;
    gbar(ep, tid, bid); ep++;               // u,v init visible everywhere

    float err = 1.0f;
    int cpt = 0;
    while (err > STOPTHR && cpt < MAXIT) {
        // v = b / (K u + eps)
        for (int i = tid; i < D / 4; i += NT)
            ((float4*)sx)[i] = __ldcg(((const float4*)d_u) + i);
        __syncthreads();
        {
            float s0, s1;
            row_dot2(d_K + (size_t)row0 * D, d_K + (size_t)(row0 + 1) * D, sx, lane, s0, s1);
            if (lane == 0) {
                d_v[row0]     = AB / (s0 + EPSF);
                d_v[row0 + 1] = AB / (s1 + EPSF);
            }
        }
        gbar(ep, tid, bid); ep++;

        // u = a / (K v + eps)
        for (int i = tid; i < D / 4; i += NT)
            ((float4*)sx)[i] = __ldcg(((const float4*)d_v) + i);
        __syncthreads();
        {
            float s0, s1;
            row_dot2(d_K + (size_t)row0 * D, d_K + (size_t)(row0 + 1) * D, sx, lane, s0, s1);
            if (lane == 0) {
                d_u[row0]     = AB / (s0 + EPSF);
                d_u[row0 + 1] = AB / (s1 + EPSF);
            }
        }
        gbar(ep, tid, bid); ep++;

        cpt++;
        if (cpt % 50 == 1) {
            // err = sum_i | v_i * (K u_new)_i - b |
            for (int i = tid; i < D / 4; i += NT)
                ((float4*)sx)[i] = __ldcg(((const float4*)d_u) + i);
            __syncthreads();
            {
                float s0, s1;
                row_dot2(d_K + (size_t)row0 * D, d_K + (size_t)(row0 + 1) * D, sx, lane, s0, s1);
                if (lane == 0) {
                    sred[wid * 2]     = fabsf(__ldcg(&d_v[row0])     * s0 - AB);
                    sred[wid * 2 + 1] = fabsf(__ldcg(&d_v[row0 + 1]) * s1 - AB);
                }
            }
            __syncthreads();
            const int chk = cpt / 50;        // 0..10
            if (tid == 0) {
                float e = 0.f;
#pragma unroll
                for (int i = 0; i < RPB; i++) e += sred[i];
                d_errpart[chk * NB + bid] = e;
            }
            gbar(ep, tid, bid); ep++;
            // identical deterministic reduction in every block -> uniform control flow
            float e = 0.f;
            for (int i = 0; i < NB; i++) e += __ldcg(&d_errpart[chk * NB + i]);
            err = e;
        }
    }
}

// ---------------- KL reduction ----------------
// Qt_ij = max(u_i K_ij v_j, 1e-6), S = sum Qt, P_ij = G_ij*(invr_i+invr_j)/2
// kl = sum P*log(P/Qt) + log(S) * sum P
__global__ void __launch_bounds__(NT) kl_partial() {
    const int tid = threadIdx.x;
    constexpr int TOT4 = D * D / 4;
    const int stride = NKB * NT;
    const float4* Kv = (const float4*)d_K;
    const float4* Gv = (const float4*)d_G;
    const float4* Vv = (const float4*)d_v;
    const float4* Rv = (const float4*)d_invr;

    float sS = 0.f, sP = 0.f, sK = 0.f;
    for (int idx4 = blockIdx.x * NT + tid; idx4 < TOT4; idx4 += stride) {
        const int i   = idx4 >> 9;          // row (512 float4 per row)
        const int c4  = idx4 & 511;
        const float4 k4 = Kv[idx4];
        const float4 g4 = Gv[idx4];
        const float4 v4 = Vv[c4];
        const float4 r4 = Rv[c4];
        const float ui  = d_u[i];
        const float iri = d_invr[i];

        float q, p;
        q = fmaxf(ui * k4.x * v4.x, 1e-6f); p = g4.x * (0.5f * (iri + r4.x));
        sS += q; sP += p; sK += p * __logf(__fdividef(p, q));
        q = fmaxf(ui * k4.y * v4.y, 1e-6f); p = g4.y * (0.5f * (iri + r4.y));
        sS += q; sP += p; sK += p * __logf(__fdividef(p, q));
        q = fmaxf(ui * k4.z * v4.z, 1e-6f); p = g4.z * (0.5f * (iri + r4.z));
        sS += q; sP += p; sK += p * __logf(__fdividef(p, q));
        q = fmaxf(ui * k4.w * v4.w, 1e-6f); p = g4.w * (0.5f * (iri + r4.w));
        sS += q; sP += p; sK += p * __logf(__fdividef(p, q));
    }

    __shared__ double sd[NT];
    const double vals[3] = {(double)sS, (double)sP, (double)sK};
#pragma unroll
    for (int t = 0; t < 3; t++) {
        sd[tid] = vals[t];
        __syncthreads();
        for (int o = NT / 2; o; o >>= 1) {
            if (tid < o) sd[tid] += sd[tid + o];
            __syncthreads();
        }
        if (tid == 0) d_part[t * NKB + blockIdx.x] = sd[0];
        __syncthreads();
    }
}

__global__ void __launch_bounds__(NKB) finalize(float* out) {
    __shared__ double sd[NKB];
    const int tid = threadIdx.x;
    double acc[3];
#pragma unroll
    for (int t = 0; t < 3; t++) {
        sd[tid] = d_part[t * NKB + tid];
        __syncthreads();
        for (int o = NKB / 2; o; o >>= 1) {
            if (tid < o) sd[tid] += sd[tid + o];
            __syncthreads();
        }
        acc[t] = sd[0];
        __syncthreads();
    }
    if (tid == 0) out[0] = (float)(acc[2] + log(acc[0]) * acc[1]);
}

// ---------------- launch ----------------
extern "C" void kernel_launch(void* const* d_in, const int* in_sizes, int n_in,
                              void* d_out, int out_size) {
    const float* theta = (const float*)d_in[0];
    const float* emb   = (const float*)d_in[1];
    float* out = (float*)d_out;

    prep<<<D, F>>>(theta, emb);
    gemm_sym<<<2 * NBLK, 256>>>(theta);
    rowsum<<<D / 8, 256>>>();
    sinkhorn_kernel<<<NB, NT>>>();
    kl_partial<<<NKB, NT>>>();
    finalize<<<1, NKB>>>(out);
}